// round 14
// baseline (speedup 1.0000x reference)
#include <cuda_runtime.h>
#include <cuda_bf16.h>
#include <math.h>

#define N_NODES 19
#define N_T     4096
#define LATENT  512
#define HID     2048
#define N_EDGES 342
#define KC      64

// ---------------- scratch (__device__ globals; no allocs allowed) -----------
__device__ __align__(16) float g_accA[N_NODES * N_T];
__device__ __align__(16) float g_accB[N_NODES * N_T];
__device__ __align__(16) float g_accC[N_NODES * N_T];
__device__ __align__(16) float g_v[LATENT];
__device__ float g_adjf[N_NODES * N_NODES]; // dense edge-count matrix [dst][src]

// ---------------- K0: adjacency + zero all accumulators ---------------------
__global__ void init_kernel(const void* __restrict__ eidx,
                            float* __restrict__ accA,
                            float* __restrict__ accB,
                            float* __restrict__ accC,
                            float* __restrict__ v) {
    int t = threadIdx.x;
    if (blockIdx.x == 0) {
        __shared__ int cnt[N_NODES * N_NODES];
        __shared__ int s_i64;
        for (int i = t; i < N_NODES * N_NODES; i += blockDim.x) cnt[i] = 0;
        if (t == 0) {
            const long long* e64 = (const long long*)eidx;
            int ok = 1;
            for (int i = 0; i < N_EDGES; ++i) {
                long long x = e64[i];
                if (x < 0 || x >= N_NODES) { ok = 0; break; }
            }
            s_i64 = ok;
        }
        __syncthreads();
        const long long* e64 = (const long long*)eidx;
        const int*       e32 = (const int*)eidx;
        for (int e = t; e < N_EDGES; e += blockDim.x) {
            int src, dst;
            if (s_i64) { src = (int)e64[e]; dst = (int)e64[N_EDGES + e]; }
            else       { src = e32[e];      dst = e32[N_EDGES + e]; }
            atomicAdd(&cnt[dst * N_NODES + src], 1);
        }
        __syncthreads();
        for (int i = t; i < N_NODES * N_NODES; i += blockDim.x)
            g_adjf[i] = (float)cnt[i];
        for (int i = t; i < LATENT; i += blockDim.x) v[i] = 0.0f;
    }
    const int n4 = (N_NODES * N_T) >> 2;
    float4 zz = make_float4(0.f, 0.f, 0.f, 0.f);
    for (int q = blockIdx.x * blockDim.x + t; q < n4;
         q += gridDim.x * blockDim.x) {
        reinterpret_cast<float4*>(accA)[q] = zz;
        reinterpret_cast<float4*>(accB)[q] = zz;
        reinterpret_cast<float4*>(accC)[q] = zz;
    }
}

// ---------------- M-split split-K GEMM body ---------------------------------
// Computes rows [M0,M1) of: Cacc += stage(Ain)[19,K] @ W[K,N] for one
// (colgroup, k-slab). 128 threads x 4 cols = 512-col tile, KC k-rows.
// W streamed by direct LDG.128 (8-deep, independent); A rows staged once in
// smem as duplicated {a,a} pairs. Per-warp instruction count per W byte is
// HALF of the 19-row kernel (the invariant all stuck variants shared).
// The m-group partner block re-reads W through L2 (no extra DRAM traffic);
// RED output rows are disjoint between m-groups.
template<int MODE, int M0, int M1>
__device__ __forceinline__ void gemm_body(
        unsigned long long* sA, float* sRaw, float* s_adj,
        const float* Ain, const float* bias, const float* W,
        float* Cacc, int K, int N) {
    constexpr int MR = M1 - M0;
    const int tid = threadIdx.x;
    const int colbase = blockIdx.x * 512;
    const int kbeg = blockIdx.y * KC;

    if (MODE != 1) {
        for (int i = tid; i < N_NODES * N_NODES; i += 128)
            s_adj[i] = g_adjf[i];
    }

    // ---- stage A rows (fused epilogue/agg), duplicated {a,a} pairs ----
    if (MODE == 1) {
        for (int i = tid; i < MR * KC; i += 128) {
            int r = i / KC, k = i - r * KC;
            float a = fmaxf(Ain[(M0 + r) * K + kbeg + k] + bias[kbeg + k], 0.0f);
            unsigned long long p;
            asm("mov.b64 %0, {%1, %1};" : "=l"(p) : "f"(a));
            sA[i] = p;
        }
        __syncthreads();
    } else {
        for (int i = tid; i < N_NODES * KC; i += 128) {
            int r = i / KC, k = i - r * KC;
            float a = Ain[r * K + kbeg + k];
            if (MODE == 2) a = fmaxf(a + bias[kbeg + k], 0.0f);
            sRaw[i] = a;
        }
        __syncthreads();
        for (int i = tid; i < MR * KC; i += 128) {
            int r = i / KC, k = i - r * KC;
            float a = sRaw[(M0 + r) * KC + k];
#pragma unroll
            for (int s = 0; s < N_NODES; ++s)
                a += s_adj[(M0 + r) * N_NODES + s] * sRaw[s * KC + k];
            unsigned long long p;
            asm("mov.b64 %0, {%1, %1};" : "=l"(p) : "f"(a));
            sA[i] = p;
        }
        __syncthreads();
    }

    // acc0[r] = cols {0,1}, acc1[r] = cols {2,3} (packed f32x2)
    unsigned long long acc0[MR], acc1[MR];
#pragma unroll
    for (int r = 0; r < MR; ++r) { acc0[r] = 0ull; acc1[r] = 0ull; }

    const ulonglong2* Wp = reinterpret_cast<const ulonglong2*>(
                               W + (size_t)kbeg * N + colbase + 4 * tid);
    const size_t wstr = (size_t)N / 4;   // row stride in ulonglong2

#pragma unroll 1
    for (int k0 = 0; k0 < KC; k0 += 8) {
        ulonglong2 wv[8];   // 8 independent LDG.128 in flight
#pragma unroll
        for (int j = 0; j < 8; ++j) wv[j] = Wp[(size_t)(k0 + j) * wstr];
#pragma unroll
        for (int kk = 0; kk < 8; kk += 2) {
            const unsigned long long* ab = sA + k0 + kk;
#pragma unroll
            for (int r = 0; r < MR; ++r) {
                ulonglong2 ap = *reinterpret_cast<const ulonglong2*>(ab + r * KC);
                asm("fma.rn.f32x2 %0, %1, %2, %0;"
                    : "+l"(acc0[r]) : "l"(ap.x), "l"(wv[kk].x));
                asm("fma.rn.f32x2 %0, %1, %2, %0;"
                    : "+l"(acc1[r]) : "l"(ap.x), "l"(wv[kk].y));
                asm("fma.rn.f32x2 %0, %1, %2, %0;"
                    : "+l"(acc0[r]) : "l"(ap.y), "l"(wv[kk + 1].x));
                asm("fma.rn.f32x2 %0, %1, %2, %0;"
                    : "+l"(acc1[r]) : "l"(ap.y), "l"(wv[kk + 1].y));
            }
        }
    }

    // ---- epilogue: one 128-bit reduction per row ----
    const int col = colbase + tid * 4;
#pragma unroll
    for (int r = 0; r < MR; ++r) {
        float2 a01 = *reinterpret_cast<float2*>(&acc0[r]);
        float2 a23 = *reinterpret_cast<float2*>(&acc1[r]);
        asm volatile("red.global.add.v4.f32 [%0], {%1, %2, %3, %4};"
                     :: "l"(Cacc + (size_t)(M0 + r) * N + col),
                        "f"(a01.x), "f"(a01.y), "f"(a23.x), "f"(a23.y)
                     : "memory");
    }
}

// grid = (N/512, K/KC, 2): z selects m-group {rows 0-9, rows 10-18}
template<int MODE>
__global__ __launch_bounds__(128) void gemm_ms(
        const float* __restrict__ Ain, const float* __restrict__ bias,
        const float* __restrict__ W, float* __restrict__ Cacc,
        float* __restrict__ zbuf, int zn, int K, int N) {
    __shared__ __align__(16) unsigned long long sA[10 * KC];
    __shared__ float sRaw[N_NODES * KC];
    __shared__ float s_adj[N_NODES * N_NODES];

    // lazy zeroing for a future accumulator
    if (zbuf) {
        int nblk = gridDim.x * gridDim.y * gridDim.z;
        int bid = (blockIdx.z * gridDim.y + blockIdx.y) * gridDim.x + blockIdx.x;
        int n4 = zn >> 2;
        float4 zz = make_float4(0.f, 0.f, 0.f, 0.f);
        for (int q = bid * 128 + threadIdx.x; q < n4; q += nblk * 128)
            reinterpret_cast<float4*>(zbuf)[q] = zz;
    }

    if (blockIdx.z == 0)
        gemm_body<MODE, 0, 10>(sA, sRaw, s_adj, Ain, bias, W, Cacc, K, N);
    else
        gemm_body<MODE, 10, 19>(sA, sRaw, s_adj, Ain, bias, W, Cacc, K, N);
}

// ---------------- FC1 fused: flat = acc + b2b (also written to out1);
//                  v[512] += flat @ Wc1 --------------------------------------
__global__ __launch_bounds__(128) void fc1_kernel(
        const float* __restrict__ acc, const float* __restrict__ b2b,
        const float* __restrict__ Wc1, float* __restrict__ v,
        float* __restrict__ out1, int rows_per) {
    const int ROWS = N_NODES * N_T;
    int t = threadIdx.x;                       // cols 4t..4t+3
    int r0 = blockIdx.x * rows_per;
    int r1 = min(r0 + rows_per, ROWS);
    float4 s = make_float4(0.f, 0.f, 0.f, 0.f);
    int i = r0;
    for (; i + 8 <= r1; i += 8) {
        float f[8];
        float4 w[8];
#pragma unroll
        for (int u = 0; u < 8; ++u) {
            f[u] = acc[i + u] + b2b[(i + u) & (N_T - 1)];
            w[u] = *reinterpret_cast<const float4*>(
                       &Wc1[(size_t)(i + u) * LATENT + 4 * t]);
        }
#pragma unroll
        for (int u = 0; u < 8; ++u) {
            if (t == ((i + u) & 127)) out1[i + u] = f[u];
            s.x += f[u] * w[u].x; s.y += f[u] * w[u].y;
            s.z += f[u] * w[u].z; s.w += f[u] * w[u].w;
        }
    }
    for (; i < r1; ++i) {
        float f = acc[i] + b2b[i & (N_T - 1)];
        if (t == (i & 127)) out1[i] = f;
        float4 w = *reinterpret_cast<const float4*>(
                       &Wc1[(size_t)i * LATENT + 4 * t]);
        s.x += f * w.x; s.y += f * w.y; s.z += f * w.z; s.w += f * w.w;
    }
    asm volatile("red.global.add.v4.f32 [%0], {%1, %2, %3, %4};"
                 :: "l"(v + 4 * t), "f"(s.x), "f"(s.y), "f"(s.z), "f"(s.w)
                 : "memory");
}

// ---------------- FC2 + sigmoid ---------------------------------------------
__global__ void fc2_kernel(const float* __restrict__ v,
                           const float* __restrict__ bc1,
                           const float* __restrict__ Wc2,
                           const float* __restrict__ bc2,
                           float* __restrict__ out) {
    __shared__ float red[LATENT];
    int j = threadIdx.x;
    red[j] = (v[j] + bc1[j]) * Wc2[j];
    __syncthreads();
    for (int s = LATENT / 2; s > 0; s >>= 1) {
        if (j < s) red[j] += red[j + s];
        __syncthreads();
    }
    if (j == 0) out[0] = 1.0f / (1.0f + expf(-(red[0] + bc2[0])));
}

// ---------------- launch ----------------------------------------------------
extern "C" void kernel_launch(void* const* d_in, const int* in_sizes, int n_in,
                              void* d_out, int out_size) {
    const float* z    = (const float*)d_in[0];
    const void*  eidx = d_in[1];
    const float* W1a  = (const float*)d_in[2];
    const float* b1a  = (const float*)d_in[3];
    const float* W1b  = (const float*)d_in[4];
    const float* b1b  = (const float*)d_in[5];
    const float* W2a  = (const float*)d_in[6];
    const float* b2a  = (const float*)d_in[7];
    const float* W2b  = (const float*)d_in[8];
    const float* b2b  = (const float*)d_in[9];
    const float* Wc1  = (const float*)d_in[10];
    const float* bc1  = (const float*)d_in[11];
    const float* Wc2  = (const float*)d_in[12];
    const float* bc2  = (const float*)d_in[13];
    float* out = (float*)d_out;

    float *accA, *accB, *accC, *v;
    cudaGetSymbolAddress((void**)&accA, g_accA);
    cudaGetSymbolAddress((void**)&accB, g_accB);
    cudaGetSymbolAddress((void**)&accC, g_accC);
    cudaGetSymbolAddress((void**)&v,    g_v);

    const int nNT = N_NODES * N_T;   // 77824

    // K0: adjacency + zero accA/accB/accC/v
    init_kernel<<<148, 256>>>(eidx, accA, accB, accC, v);

    // g1a: accA = agg(z) @ W1a          [19,512]x[512,2048]   64 blocks
    gemm_ms<0><<<dim3(HID / 512, LATENT / KC, 2), 128>>>(
        z, nullptr, W1a, accA, nullptr, 0, LATENT, HID);

    // g1b: accB = relu(accA+b1a) @ W1b  [19,2048]x[2048,2048] 256 blocks
    gemm_ms<1><<<dim3(HID / 512, HID / KC, 2), 128>>>(
        accA, b1a, W1b, accB, nullptr, 0, HID, HID);

    // g2a: accC = agg(relu(accB+b1b)) @ W2a  [19,2048]x[2048,4096] 512 blocks
    //      (also lazily zeroes accA for g2b)
    gemm_ms<2><<<dim3(N_T / 512, HID / KC, 2), 128>>>(
        accB, b1b, W2a, accC, accA, nNT, HID, N_T);

    // g2b: accA = relu(accC+b2a) @ W2b  [19,4096]x[4096,4096] 1024 blocks
    gemm_ms<1><<<dim3(N_T / 512, N_T / KC, 2), 128>>>(
        accC, b2a, W2b, accA, nullptr, 0, N_T, N_T);

    // classifier: epilogue (+b2b, write out[1:]) fused into FC1
    fc1_kernel<<<1184, 128>>>(accA, b2b, Wc1, v, out + 1, 66);
    fc2_kernel<<<1, 512>>>(v, bc1, Wc2, bc2, out);
}

// round 15
// speedup vs baseline: 1.2116x; 1.2116x over previous
#include <cuda_runtime.h>
#include <cuda_bf16.h>
#include <math.h>

#define N_NODES 19
#define N_T     4096
#define LATENT  512
#define HID     2048
#define N_EDGES 342

// ---------------- scratch (__device__ globals; no allocs allowed) -----------
__device__ __align__(16) float g_accA[N_NODES * N_T];
__device__ __align__(16) float g_accB[N_NODES * N_T];
__device__ __align__(16) float g_accC[N_NODES * N_T];
__device__ __align__(16) float g_v[LATENT];
__device__ float g_adjf[N_NODES * N_NODES]; // dense edge-count matrix [dst][src]

// ---------------- K0: adjacency + zero all accumulators ---------------------
__global__ void init_kernel(const void* __restrict__ eidx,
                            float* __restrict__ accA,
                            float* __restrict__ accB,
                            float* __restrict__ accC,
                            float* __restrict__ v) {
    int t = threadIdx.x;
    if (blockIdx.x == 0) {
        __shared__ int cnt[N_NODES * N_NODES];
        __shared__ int s_i64;
        for (int i = t; i < N_NODES * N_NODES; i += blockDim.x) cnt[i] = 0;
        if (t == 0) {
            const long long* e64 = (const long long*)eidx;
            int ok = 1;
            for (int i = 0; i < N_EDGES; ++i) {
                long long x = e64[i];
                if (x < 0 || x >= N_NODES) { ok = 0; break; }
            }
            s_i64 = ok;
        }
        __syncthreads();
        const long long* e64 = (const long long*)eidx;
        const int*       e32 = (const int*)eidx;
        for (int e = t; e < N_EDGES; e += blockDim.x) {
            int src, dst;
            if (s_i64) { src = (int)e64[e]; dst = (int)e64[N_EDGES + e]; }
            else       { src = e32[e];      dst = e32[N_EDGES + e]; }
            atomicAdd(&cnt[dst * N_NODES + src], 1);
        }
        __syncthreads();
        for (int i = t; i < N_NODES * N_NODES; i += blockDim.x)
            g_adjf[i] = (float)cnt[i];
        for (int i = t; i < LATENT; i += blockDim.x) v[i] = 0.0f;
    }
    const int n4 = (N_NODES * N_T) >> 2;
    float4 zz = make_float4(0.f, 0.f, 0.f, 0.f);
    for (int q = blockIdx.x * blockDim.x + t; q < n4;
         q += gridDim.x * blockDim.x) {
        reinterpret_cast<float4*>(accA)[q] = zz;
        reinterpret_cast<float4*>(accB)[q] = zz;
        reinterpret_cast<float4*>(accC)[q] = zz;
    }
}

// ---------------- high-occupancy barrier-free split-K GEMM ------------------
// Cacc += stage(Ain)[19, K] @ W[K, N].  128 threads x 2 cols = 256-col tile.
// NEW (R15): same barrier-free direct-LDG structure as R12, but run at
// fc1's occupancy: ~72 regs (acc[19] u64), launch_bounds(128,7), grids of
// 1024+ blocks -> ~7 blocks = 28 warps/SM. In-flight bytes/SM ~57KB (vs
// ~8KB in every previous GEMM variant). W via 8 independent LDG.64/iter;
// A staged once in smem as {a,a} pairs (single barrier, outside mainloop).
// Epilogue: one red.global.add.v2.f32 per row.
// MODE 0: stage = agg(Ain); 1: relu(Ain+bias); 2: agg(relu(Ain+bias)).
template<int KC, int MODE>
__global__ __launch_bounds__(128, 7) void gemm_hiocc(
        const float* __restrict__ Ain, const float* __restrict__ bias,
        const float* __restrict__ W, float* __restrict__ Cacc,
        float* __restrict__ zbuf, int zn, int K, int N) {
    __shared__ __align__(16) unsigned long long sA[N_NODES * KC];
    __shared__ float sRaw[(MODE != 1) ? N_NODES * KC : 1];
    __shared__ float s_adj[(MODE != 1) ? N_NODES * N_NODES : 1];

    const int tid = threadIdx.x;
    const int colbase = blockIdx.x * 256;
    const int kbeg = blockIdx.y * KC;

    // lazy zeroing for a future accumulator
    if (zbuf) {
        int n4 = zn >> 2;
        float4 zz = make_float4(0.f, 0.f, 0.f, 0.f);
        for (int q = (blockIdx.y * gridDim.x + blockIdx.x) * 128 + tid;
             q < n4; q += gridDim.x * gridDim.y * 128)
            reinterpret_cast<float4*>(zbuf)[q] = zz;
    }
    if (MODE != 1) {
        for (int i = tid; i < N_NODES * N_NODES; i += 128)
            s_adj[i] = g_adjf[i];
    }

    // ---- stage A slab once (fused epilogue/agg), duplicated {a,a} pairs ----
    if (MODE == 1) {
        for (int i = tid; i < N_NODES * KC; i += 128) {
            int r = i / KC, k = i - r * KC;
            float a = fmaxf(Ain[r * K + kbeg + k] + bias[kbeg + k], 0.0f);
            unsigned long long p;
            asm("mov.b64 %0, {%1, %1};" : "=l"(p) : "f"(a));
            sA[i] = p;
        }
        __syncthreads();
    } else {
        for (int i = tid; i < N_NODES * KC; i += 128) {
            int r = i / KC, k = i - r * KC;
            float a = Ain[r * K + kbeg + k];
            if (MODE == 2) a = fmaxf(a + bias[kbeg + k], 0.0f);
            sRaw[i] = a;
        }
        __syncthreads();
        for (int i = tid; i < N_NODES * KC; i += 128) {
            int r = i / KC, k = i - r * KC;
            float a = sRaw[r * KC + k];
#pragma unroll
            for (int s = 0; s < N_NODES; ++s)
                a += s_adj[r * N_NODES + s] * sRaw[s * KC + k];
            unsigned long long p;
            asm("mov.b64 %0, {%1, %1};" : "=l"(p) : "f"(a));
            sA[i] = p;
        }
        __syncthreads();
    }
    // mainloop below: no barriers, fully independent per thread

    unsigned long long acc[N_NODES];
#pragma unroll
    for (int r = 0; r < N_NODES; ++r) acc[r] = 0ull;

    const float* Wp = W + (size_t)kbeg * N + colbase + 2 * tid;

#pragma unroll 1
    for (int k0 = 0; k0 < KC; k0 += 8) {
        // 8 independent LDG.64 in flight
        unsigned long long w[8];
#pragma unroll
        for (int j = 0; j < 8; ++j)
            w[j] = *reinterpret_cast<const unsigned long long*>(
                       Wp + (size_t)(k0 + j) * N);

#pragma unroll
        for (int kk = 0; kk < 8; kk += 2) {
            const unsigned long long* ab = sA + k0 + kk;
#pragma unroll
            for (int r = 0; r < N_NODES; ++r) {
                ulonglong2 ap = *reinterpret_cast<const ulonglong2*>(ab + r * KC);
                asm("fma.rn.f32x2 %0, %1, %2, %0;"
                    : "+l"(acc[r]) : "l"(ap.x), "l"(w[kk]));
                asm("fma.rn.f32x2 %0, %1, %2, %0;"
                    : "+l"(acc[r]) : "l"(ap.y), "l"(w[kk + 1]));
            }
        }
    }

    // ---- epilogue: one 64-bit reduction per row ----
    const int col = colbase + tid * 2;
#pragma unroll
    for (int r = 0; r < N_NODES; ++r) {
        float2 p = *reinterpret_cast<float2*>(&acc[r]);
        asm volatile("red.global.add.v2.f32 [%0], {%1, %2};"
                     :: "l"(Cacc + (size_t)r * N + col), "f"(p.x), "f"(p.y)
                     : "memory");
    }
}

// ---------------- FC1 fused: flat = acc + b2b (also written to out1);
//                  v[512] += flat @ Wc1 --------------------------------------
__global__ __launch_bounds__(128) void fc1_kernel(
        const float* __restrict__ acc, const float* __restrict__ b2b,
        const float* __restrict__ Wc1, float* __restrict__ v,
        float* __restrict__ out1, int rows_per) {
    const int ROWS = N_NODES * N_T;
    int t = threadIdx.x;                       // cols 4t..4t+3
    int r0 = blockIdx.x * rows_per;
    int r1 = min(r0 + rows_per, ROWS);
    float4 s = make_float4(0.f, 0.f, 0.f, 0.f);
    int i = r0;
    for (; i + 8 <= r1; i += 8) {
        float f[8];
        float4 w[8];
#pragma unroll
        for (int u = 0; u < 8; ++u) {
            f[u] = acc[i + u] + b2b[(i + u) & (N_T - 1)];
            w[u] = *reinterpret_cast<const float4*>(
                       &Wc1[(size_t)(i + u) * LATENT + 4 * t]);
        }
#pragma unroll
        for (int u = 0; u < 8; ++u) {
            if (t == ((i + u) & 127)) out1[i + u] = f[u];
            s.x += f[u] * w[u].x; s.y += f[u] * w[u].y;
            s.z += f[u] * w[u].z; s.w += f[u] * w[u].w;
        }
    }
    for (; i < r1; ++i) {
        float f = acc[i] + b2b[i & (N_T - 1)];
        if (t == (i & 127)) out1[i] = f;
        float4 w = *reinterpret_cast<const float4*>(
                       &Wc1[(size_t)i * LATENT + 4 * t]);
        s.x += f * w.x; s.y += f * w.y; s.z += f * w.z; s.w += f * w.w;
    }
    asm volatile("red.global.add.v4.f32 [%0], {%1, %2, %3, %4};"
                 :: "l"(v + 4 * t), "f"(s.x), "f"(s.y), "f"(s.z), "f"(s.w)
                 : "memory");
}

// ---------------- FC2 + sigmoid ---------------------------------------------
__global__ void fc2_kernel(const float* __restrict__ v,
                           const float* __restrict__ bc1,
                           const float* __restrict__ Wc2,
                           const float* __restrict__ bc2,
                           float* __restrict__ out) {
    __shared__ float red[LATENT];
    int j = threadIdx.x;
    red[j] = (v[j] + bc1[j]) * Wc2[j];
    __syncthreads();
    for (int s = LATENT / 2; s > 0; s >>= 1) {
        if (j < s) red[j] += red[j + s];
        __syncthreads();
    }
    if (j == 0) out[0] = 1.0f / (1.0f + expf(-(red[0] + bc2[0])));
}

// ---------------- launch ----------------------------------------------------
extern "C" void kernel_launch(void* const* d_in, const int* in_sizes, int n_in,
                              void* d_out, int out_size) {
    const float* z    = (const float*)d_in[0];
    const void*  eidx = d_in[1];
    const float* W1a  = (const float*)d_in[2];
    const float* b1a  = (const float*)d_in[3];
    const float* W1b  = (const float*)d_in[4];
    const float* b1b  = (const float*)d_in[5];
    const float* W2a  = (const float*)d_in[6];
    const float* b2a  = (const float*)d_in[7];
    const float* W2b  = (const float*)d_in[8];
    const float* b2b  = (const float*)d_in[9];
    const float* Wc1  = (const float*)d_in[10];
    const float* bc1  = (const float*)d_in[11];
    const float* Wc2  = (const float*)d_in[12];
    const float* bc2  = (const float*)d_in[13];
    float* out = (float*)d_out;

    float *accA, *accB, *accC, *v;
    cudaGetSymbolAddress((void**)&accA, g_accA);
    cudaGetSymbolAddress((void**)&accB, g_accB);
    cudaGetSymbolAddress((void**)&accC, g_accC);
    cudaGetSymbolAddress((void**)&v,    g_v);

    const int nNT = N_NODES * N_T;   // 77824

    // K0: adjacency + zero accA/accB/accC/v
    init_kernel<<<148, 256>>>(eidx, accA, accB, accC, v);

    // g1a: accA = agg(z) @ W1a          [19,512]x[512,2048]   128 blocks
    gemm_hiocc<32, 0><<<dim3(HID / 256, LATENT / 32), 128>>>(
        z, nullptr, W1a, accA, nullptr, 0, LATENT, HID);

    // g1b: accB = relu(accA+b1a) @ W1b  [19,2048]x[2048,2048] 1024 blocks
    gemm_hiocc<16, 1><<<dim3(HID / 256, HID / 16), 128>>>(
        accA, b1a, W1b, accB, nullptr, 0, HID, HID);

    // g2a: accC = agg(relu(accB+b1b)) @ W2a  [19,2048]x[2048,4096] 1024 blocks
    //      (also lazily zeroes accA for g2b)
    gemm_hiocc<32, 2><<<dim3(N_T / 256, HID / 32), 128>>>(
        accB, b1b, W2a, accC, accA, nNT, HID, N_T);

    // g2b: accA = relu(accC+b2a) @ W2b  [19,4096]x[4096,4096] 1024 blocks
    gemm_hiocc<64, 1><<<dim3(N_T / 256, N_T / 64), 128>>>(
        accC, b2a, W2b, accA, nullptr, 0, N_T, N_T);

    // classifier: epilogue (+b2b, write out[1:]) fused into FC1
    fc1_kernel<<<1184, 128>>>(accA, b2b, Wc1, v, out + 1, 66);
    fc2_kernel<<<1, 512>>>(v, bc1, Wc2, bc2, out);
}

// round 16
// speedup vs baseline: 1.2759x; 1.0531x over previous
#include <cuda_runtime.h>
#include <cuda_bf16.h>
#include <math.h>

#define N_NODES 19
#define N_T     4096
#define LATENT  512
#define HID     2048
#define N_EDGES 342

// ---------------- scratch (__device__ globals; no allocs allowed) -----------
__device__ __align__(16) float g_accA[N_NODES * N_T];
__device__ __align__(16) float g_accB[N_NODES * N_T];
__device__ __align__(16) float g_accC[N_NODES * N_T];
__device__ __align__(16) float g_v[LATENT];
__device__ float g_adjf[N_NODES * N_NODES]; // dense edge-count matrix [dst][src]

// ---------------- K0: adjacency + zero all accumulators ---------------------
__global__ void init_kernel(const void* __restrict__ eidx,
                            float* __restrict__ accA,
                            float* __restrict__ accB,
                            float* __restrict__ accC,
                            float* __restrict__ v) {
    int t = threadIdx.x;
    if (blockIdx.x == 0) {
        __shared__ int cnt[N_NODES * N_NODES];
        __shared__ int s_i64;
        for (int i = t; i < N_NODES * N_NODES; i += blockDim.x) cnt[i] = 0;
        if (t == 0) {
            const long long* e64 = (const long long*)eidx;
            int ok = 1;
            for (int i = 0; i < N_EDGES; ++i) {
                long long x = e64[i];
                if (x < 0 || x >= N_NODES) { ok = 0; break; }
            }
            s_i64 = ok;
        }
        __syncthreads();
        const long long* e64 = (const long long*)eidx;
        const int*       e32 = (const int*)eidx;
        for (int e = t; e < N_EDGES; e += blockDim.x) {
            int src, dst;
            if (s_i64) { src = (int)e64[e]; dst = (int)e64[N_EDGES + e]; }
            else       { src = e32[e];      dst = e32[N_EDGES + e]; }
            atomicAdd(&cnt[dst * N_NODES + src], 1);
        }
        __syncthreads();
        for (int i = t; i < N_NODES * N_NODES; i += blockDim.x)
            g_adjf[i] = (float)cnt[i];
        for (int i = t; i < LATENT; i += blockDim.x) v[i] = 0.0f;
    }
    const int n4 = (N_NODES * N_T) >> 2;
    float4 zz = make_float4(0.f, 0.f, 0.f, 0.f);
    for (int q = blockIdx.x * blockDim.x + t; q < n4;
         q += gridDim.x * blockDim.x) {
        reinterpret_cast<float4*>(accA)[q] = zz;
        reinterpret_cast<float4*>(accB)[q] = zz;
        reinterpret_cast<float4*>(accC)[q] = zz;
    }
}

// ---------------- 4-col high-occupancy barrier-free split-K GEMM ------------
// Cacc += stage(Ain)[19, K] @ W[K, N].  128 threads x 4 cols = 512-col tile.
// NEW (R16): R12's 4-col shape (13.5 L1 wavefronts / 512B of W -- half of
// R15's 2-col 23) run at R15's occupancy (launch_bounds(128,4), grids of
// 512-1024 blocks -> 4 blocks = 16 warps/SM). W: double-buffered pair of
// LDG.128 per 2k; A staged once in smem as {a,a} pairs (single barrier).
// Epilogue: one red.global.add.v4.f32 per row.
// MODE 0: stage = agg(Ain); 1: relu(Ain+bias); 2: agg(relu(Ain+bias)).
template<int KC, int MODE>
__global__ __launch_bounds__(128, 4) void gemm_w4(
        const float* __restrict__ Ain, const float* __restrict__ bias,
        const float* __restrict__ W, float* __restrict__ Cacc,
        float* __restrict__ zbuf, int zn, int K, int N) {
    __shared__ __align__(16) unsigned long long sA[N_NODES * KC];
    __shared__ float sRaw[(MODE != 1) ? N_NODES * KC : 1];
    __shared__ float s_adj[(MODE != 1) ? N_NODES * N_NODES : 1];

    const int tid = threadIdx.x;
    const int colbase = blockIdx.x * 512;
    const int kbeg = blockIdx.y * KC;

    // lazy zeroing for a future accumulator
    if (zbuf) {
        int n4 = zn >> 2;
        float4 zz = make_float4(0.f, 0.f, 0.f, 0.f);
        for (int q = (blockIdx.y * gridDim.x + blockIdx.x) * 128 + tid;
             q < n4; q += gridDim.x * gridDim.y * 128)
            reinterpret_cast<float4*>(zbuf)[q] = zz;
    }
    if (MODE != 1) {
        for (int i = tid; i < N_NODES * N_NODES; i += 128)
            s_adj[i] = g_adjf[i];
    }

    // ---- stage A slab once (fused epilogue/agg), duplicated {a,a} pairs ----
    if (MODE == 1) {
        for (int i = tid; i < N_NODES * KC; i += 128) {
            int r = i / KC, k = i - r * KC;
            float a = fmaxf(Ain[r * K + kbeg + k] + bias[kbeg + k], 0.0f);
            unsigned long long p;
            asm("mov.b64 %0, {%1, %1};" : "=l"(p) : "f"(a));
            sA[i] = p;
        }
        __syncthreads();
    } else {
        for (int i = tid; i < N_NODES * KC; i += 128) {
            int r = i / KC, k = i - r * KC;
            float a = Ain[r * K + kbeg + k];
            if (MODE == 2) a = fmaxf(a + bias[kbeg + k], 0.0f);
            sRaw[i] = a;
        }
        __syncthreads();
        for (int i = tid; i < N_NODES * KC; i += 128) {
            int r = i / KC, k = i - r * KC;
            float a = sRaw[r * KC + k];
#pragma unroll
            for (int s = 0; s < N_NODES; ++s)
                a += s_adj[r * N_NODES + s] * sRaw[s * KC + k];
            unsigned long long p;
            asm("mov.b64 %0, {%1, %1};" : "=l"(p) : "f"(a));
            sA[i] = p;
        }
        __syncthreads();
    }
    // mainloop below: no barriers, fully independent per thread

    // acc0[r] = cols {0,1}, acc1[r] = cols {2,3} (packed f32x2)
    unsigned long long acc0[N_NODES], acc1[N_NODES];
#pragma unroll
    for (int r = 0; r < N_NODES; ++r) { acc0[r] = 0ull; acc1[r] = 0ull; }

    const ulonglong2* Wp = reinterpret_cast<const ulonglong2*>(
                               W + (size_t)kbeg * N + colbase + 4 * tid);
    const size_t wstr = (size_t)N / 4;   // W row stride in ulonglong2

    // double-buffered W pair (k, k+1)
    ulonglong2 wv0 = Wp[0];
    ulonglong2 wv1 = Wp[wstr];

#pragma unroll 1
    for (int k0 = 0; k0 < KC; k0 += 2) {
        ulonglong2 nw0, nw1;
        if (k0 + 2 < KC) {           // prefetch next pair
            nw0 = Wp[(size_t)(k0 + 2) * wstr];
            nw1 = Wp[(size_t)(k0 + 3) * wstr];
        }
        const unsigned long long* ab = sA + k0;
#pragma unroll
        for (int r = 0; r < N_NODES; ++r) {
            ulonglong2 ap = *reinterpret_cast<const ulonglong2*>(ab + r * KC);
            asm("fma.rn.f32x2 %0, %1, %2, %0;"
                : "+l"(acc0[r]) : "l"(ap.x), "l"(wv0.x));
            asm("fma.rn.f32x2 %0, %1, %2, %0;"
                : "+l"(acc1[r]) : "l"(ap.x), "l"(wv0.y));
            asm("fma.rn.f32x2 %0, %1, %2, %0;"
                : "+l"(acc0[r]) : "l"(ap.y), "l"(wv1.x));
            asm("fma.rn.f32x2 %0, %1, %2, %0;"
                : "+l"(acc1[r]) : "l"(ap.y), "l"(wv1.y));
        }
        wv0 = nw0; wv1 = nw1;
    }

    // ---- epilogue: one 128-bit reduction per row ----
    const int col = colbase + tid * 4;
#pragma unroll
    for (int r = 0; r < N_NODES; ++r) {
        float2 a01 = *reinterpret_cast<float2*>(&acc0[r]);
        float2 a23 = *reinterpret_cast<float2*>(&acc1[r]);
        asm volatile("red.global.add.v4.f32 [%0], {%1, %2, %3, %4};"
                     :: "l"(Cacc + (size_t)r * N + col),
                        "f"(a01.x), "f"(a01.y), "f"(a23.x), "f"(a23.y)
                     : "memory");
    }
}

// ---------------- FC1 fused: flat = acc + b2b (also written to out1);
//                  v[512] += flat @ Wc1 --------------------------------------
__global__ __launch_bounds__(128) void fc1_kernel(
        const float* __restrict__ acc, const float* __restrict__ b2b,
        const float* __restrict__ Wc1, float* __restrict__ v,
        float* __restrict__ out1, int rows_per) {
    const int ROWS = N_NODES * N_T;
    int t = threadIdx.x;                       // cols 4t..4t+3
    int r0 = blockIdx.x * rows_per;
    int r1 = min(r0 + rows_per, ROWS);
    float4 s = make_float4(0.f, 0.f, 0.f, 0.f);
    int i = r0;
    for (; i + 8 <= r1; i += 8) {
        float f[8];
        float4 w[8];
#pragma unroll
        for (int u = 0; u < 8; ++u) {
            f[u] = acc[i + u] + b2b[(i + u) & (N_T - 1)];
            w[u] = *reinterpret_cast<const float4*>(
                       &Wc1[(size_t)(i + u) * LATENT + 4 * t]);
        }
#pragma unroll
        for (int u = 0; u < 8; ++u) {
            if (t == ((i + u) & 127)) out1[i + u] = f[u];
            s.x += f[u] * w[u].x; s.y += f[u] * w[u].y;
            s.z += f[u] * w[u].z; s.w += f[u] * w[u].w;
        }
    }
    for (; i < r1; ++i) {
        float f = acc[i] + b2b[i & (N_T - 1)];
        if (t == (i & 127)) out1[i] = f;
        float4 w = *reinterpret_cast<const float4*>(
                       &Wc1[(size_t)i * LATENT + 4 * t]);
        s.x += f * w.x; s.y += f * w.y; s.z += f * w.z; s.w += f * w.w;
    }
    asm volatile("red.global.add.v4.f32 [%0], {%1, %2, %3, %4};"
                 :: "l"(v + 4 * t), "f"(s.x), "f"(s.y), "f"(s.z), "f"(s.w)
                 : "memory");
}

// ---------------- FC2 + sigmoid ---------------------------------------------
__global__ void fc2_kernel(const float* __restrict__ v,
                           const float* __restrict__ bc1,
                           const float* __restrict__ Wc2,
                           const float* __restrict__ bc2,
                           float* __restrict__ out) {
    __shared__ float red[LATENT];
    int j = threadIdx.x;
    red[j] = (v[j] + bc1[j]) * Wc2[j];
    __syncthreads();
    for (int s = LATENT / 2; s > 0; s >>= 1) {
        if (j < s) red[j] += red[j + s];
        __syncthreads();
    }
    if (j == 0) out[0] = 1.0f / (1.0f + expf(-(red[0] + bc2[0])));
}

// ---------------- launch ----------------------------------------------------
extern "C" void kernel_launch(void* const* d_in, const int* in_sizes, int n_in,
                              void* d_out, int out_size) {
    const float* z    = (const float*)d_in[0];
    const void*  eidx = d_in[1];
    const float* W1a  = (const float*)d_in[2];
    const float* b1a  = (const float*)d_in[3];
    const float* W1b  = (const float*)d_in[4];
    const float* b1b  = (const float*)d_in[5];
    const float* W2a  = (const float*)d_in[6];
    const float* b2a  = (const float*)d_in[7];
    const float* W2b  = (const float*)d_in[8];
    const float* b2b  = (const float*)d_in[9];
    const float* Wc1  = (const float*)d_in[10];
    const float* bc1  = (const float*)d_in[11];
    const float* Wc2  = (const float*)d_in[12];
    const float* bc2  = (const float*)d_in[13];
    float* out = (float*)d_out;

    float *accA, *accB, *accC, *v;
    cudaGetSymbolAddress((void**)&accA, g_accA);
    cudaGetSymbolAddress((void**)&accB, g_accB);
    cudaGetSymbolAddress((void**)&accC, g_accC);
    cudaGetSymbolAddress((void**)&v,    g_v);

    const int nNT = N_NODES * N_T;   // 77824

    // K0: adjacency + zero accA/accB/accC/v
    init_kernel<<<148, 256>>>(eidx, accA, accB, accC, v);

    // g1a: accA = agg(z) @ W1a          [19,512]x[512,2048]   128 blocks
    gemm_w4<16, 0><<<dim3(HID / 512, LATENT / 16), 128>>>(
        z, nullptr, W1a, accA, nullptr, 0, LATENT, HID);

    // g1b: accB = relu(accA+b1a) @ W1b  [19,2048]x[2048,2048] 512 blocks
    gemm_w4<16, 1><<<dim3(HID / 512, HID / 16), 128>>>(
        accA, b1a, W1b, accB, nullptr, 0, HID, HID);

    // g2a: accC = agg(relu(accB+b1b)) @ W2a  [19,2048]x[2048,4096] 1024 blocks
    //      (also lazily zeroes accA for g2b)
    gemm_w4<16, 2><<<dim3(N_T / 512, HID / 16), 128>>>(
        accB, b1b, W2a, accC, accA, nNT, HID, N_T);

    // g2b: accA = relu(accC+b2a) @ W2b  [19,4096]x[4096,4096] 1024 blocks
    gemm_w4<32, 1><<<dim3(N_T / 512, N_T / 32), 128>>>(
        accC, b2a, W2b, accA, nullptr, 0, N_T, N_T);

    // classifier: epilogue (+b2b, write out[1:]) fused into FC1
    fc1_kernel<<<1184, 128>>>(accA, b2b, Wc1, v, out + 1, 66);
    fc2_kernel<<<1, 512>>>(v, bc1, Wc2, bc2, out);
}